// round 4
// baseline (speedup 1.0000x reference)
#include <cuda_runtime.h>

#define BDIM 512
#define LL   2048
#define CC   12
#define NDIL 8
#define KK   8
#define GG   32
#define NCP  6

#define ROWBUF 3072                               // floats per warp row buffer
#define SCAT_OFF (16 * ROWBUF)                    // 49152 floats
#define SMEM_FLOATS (SCAT_OFF + 16 * KK * 32 * 2) // 57344 floats = 229376 B

typedef unsigned long long u64;

__device__ __forceinline__ int swz(int x){ return x ^ (((x>>5)^(x>>10))&31); }

__device__ __forceinline__ u64 pack2(float lo, float hi){
  u64 r; asm("mov.b64 %0, {%1,%2};" : "=l"(r) : "f"(lo), "f"(hi)); return r;
}
__device__ __forceinline__ void unpack2(u64 v, float& lo, float& hi){
  asm("mov.b64 {%0,%1}, %2;" : "=f"(lo), "=f"(hi) : "l"(v));
}
__device__ __forceinline__ u64 ffma2(u64 a, u64 b, u64 c){
  u64 r; asm("fma.rn.f32x2 %0, %1, %2, %3;" : "=l"(r) : "l"(a), "l"(b), "l"(c)); return r;
}
__device__ __forceinline__ u64 fmul2(u64 a, u64 b){
  u64 r; asm("mul.rn.f32x2 %0, %1, %2;" : "=l"(r) : "l"(a), "l"(b)); return r;
}

// 8 dot products; window already dup-packed as u64 (v,v)
__device__ __forceinline__ void dots8d(const u64 pk[36], const u64 w2[9], float a[8]){
  u64 a0 = fmul2(pk[0],  w2[0]), a1 = fmul2(pk[9],  w2[0]),
      a2 = fmul2(pk[18], w2[0]), a3 = fmul2(pk[27], w2[0]);
  #pragma unroll
  for (int t = 1; t < 9; ++t){
    a0 = ffma2(pk[t],      w2[t], a0);
    a1 = ffma2(pk[9 + t],  w2[t], a1);
    a2 = ffma2(pk[18 + t], w2[t], a2);
    a3 = ffma2(pk[27 + t], w2[t], a3);
  }
  unpack2(a0, a[0], a[1]); unpack2(a1, a[2], a[3]);
  unpack2(a2, a[4], a[5]); unpack2(a3, a[6], a[7]);
}

// first-occurrence argmax/argmin over 8 (matches jnp tie-breaking, exact)
__device__ __forceinline__ void chain8(const float a[8], float& m, int& mi, int& ni){
  m = a[0]; float n = a[0]; mi = 0; ni = 0;
  #pragma unroll
  for (int k = 1; k < 8; ++k){
    bool gt = a[k] > m;
    bool lt = a[k] < n;
    m = fmaxf(m, a[k]);
    n = fminf(n, a[k]);
    mi = gt ? k : mi;
    ni = lt ? k : ni;
  }
}

template<int DI>
__device__ __forceinline__ void run_di(const float* __restrict__ X,
                                       const float* __restrict__ W,
                                       const int*   __restrict__ I,
                                       float* __restrict__ out,
                                       float* __restrict__ row,
                                       float* __restrict__ scm,
                                       float* __restrict__ scn,
                                       int b, int warp, int lane)
{
  constexpr int d    = 1 << DI;
  constexpr int P    = LL >> DI;
  constexpr int logP = 11 - DI;
  constexpr int SEG  = (P < 64) ? P : 64;

  const float* Xb = X + (size_t)b * CC * LL;

  for (int it = 0; it < 4; ++it){
    const int task = warp * 4 + it;
    const int diff = task >> 5, g = task & 31;

    // ---------- build padded presummed row (warp-private) ----------
    const int* Ip = I + ((DI * 2 + diff) * GG + g) * NCP;
    const float* c0 = Xb + Ip[0] * LL;
    const float* c1 = Xb + Ip[1] * LL;
    const float* c2 = Xb + Ip[2] * LL;
    const float* c3 = Xb + Ip[3] * LL;
    const float* c4 = Xb + Ip[4] * LL;
    const float* c5 = Xb + Ip[5] * LL;

    // zero whole buffer (pads included); swizzle-invariant since all-zero
    #pragma unroll
    for (int z = 0; z < ROWBUF / 4; z += 32)
      *(float4*)(row + 4 * (z + lane)) = make_float4(0.f, 0.f, 0.f, 0.f);
    __syncwarp();

    // descending chunks so the diff boundary carry (s[chunk_end]) is known
    float carry = 0.0f;
    #pragma unroll 1
    for (int ch = 15; ch >= 0; --ch){
      const int l0 = ch * 128 + lane * 4;
      float4 a0 = *(const float4*)(c0 + l0);
      float4 a1 = *(const float4*)(c1 + l0);
      float4 a2 = *(const float4*)(c2 + l0);
      float4 a3 = *(const float4*)(c3 + l0);
      float4 a4 = *(const float4*)(c4 + l0);
      float4 a5 = *(const float4*)(c5 + l0);
      float4 s;
      s.x = ((a0.x + a1.x) + (a2.x + a3.x)) + (a4.x + a5.x);
      s.y = ((a0.y + a1.y) + (a2.y + a3.y)) + (a4.y + a5.y);
      s.z = ((a0.z + a1.z) + (a2.z + a3.z)) + (a4.z + a5.z);
      s.w = ((a0.w + a1.w) + (a2.w + a3.w)) + (a4.w + a5.w);

      float nxt = __shfl_down_sync(0xffffffffu, s.x, 1);
      float bc  = __shfl_sync(0xffffffffu, s.x, 0);   // s[ch*128] for next (lower) chunk
      if (lane == 31) nxt = carry;
      carry = bc;

      float4 v = s;
      if (diff){
        v.x = s.y - s.x; v.y = s.z - s.y; v.z = s.w - s.z; v.w = nxt - s.w;
      }
      row[swz(l0 + 4 * d + 0)] = v.x;
      row[swz(l0 + 4 * d + 1)] = v.y;
      row[swz(l0 + 4 * d + 2)] = v.z;
      row[swz(l0 + 4 * d + 3)] = v.w;
    }
    if (diff && lane == 0) row[swz(2047 + 4 * d)] = 0.0f;  // diff stream convention
    __syncwarp();

    // ---------- weights: 8 kernels x 9 taps, packed in k-pairs ----------
    const float* Wp = W + (size_t)((DI * 2 + diff) * (KK * GG) + g * KK) * 9;
    u64 pk[36];
    #pragma unroll
    for (int j = 0; j < 4; ++j)
      #pragma unroll
      for (int t = 0; t < 9; ++t)
        pk[j * 9 + t] = pack2(__ldg(Wp + (2 * j) * 9 + t),
                              __ldg(Wp + (2 * j + 1) * 9 + t));

    // zero this warp's private scatter columns (lane-private, no sync)
    #pragma unroll
    for (int k = 0; k < KK; ++k){
      scm[(k << 5) + lane] = 0.0f;
      scn[(k << 5) + lane] = 0.0f;
    }

    // ---------- convolution: phase-major, sliding dup-packed window ----------
    #pragma unroll 1
    for (int s0 = 0; s0 < 64; s0 += SEG){
      const int q     = lane * 64 + s0;
      const int phase = q >> logP;
      const int i0    = q & (P - 1);
      int l = phase + i0 * d;          // taps live at row[l + t*d], t=0..8

      u64 w2[9];
      #pragma unroll
      for (int t = 0; t < 9; ++t){
        float v = row[swz(l + t * d)];
        w2[t] = pack2(v, v);
      }

      #pragma unroll 1
      for (int blk = 0; blk < SEG / 8; ++blk){
        #pragma unroll
        for (int u = 0; u < 8; ++u){
          float a8[8]; float m; int mi, ni;
          dots8d(pk, w2, a8);
          chain8(a8, m, mi, ni);

          scm[(mi << 5) + lane] += m;
          scn[(ni << 5) + lane] += 1.0f;

          float nv = row[swz(l + 9 * d)];
          l += d;
          #pragma unroll
          for (int t = 0; t < 8; ++t) w2[t] = w2[t + 1];
          w2[8] = pack2(nv, nv);
        }
      }
    }

    // diff stream Lout = 2047: subtract phantom position l = 2047 (exact cancel)
    if (diff && lane == 31){
      u64 w9[9];
      #pragma unroll
      for (int t = 0; t < 9; ++t){
        float v = row[swz(2047 + t * d)];
        w9[t] = pack2(v, v);
      }
      float a8[8]; float m; int mi, ni;
      dots8d(pk, w9, a8);
      chain8(a8, m, mi, ni);
      scm[(mi << 5) + 31] -= m;
      scn[(ni << 5) + 31] -= 1.0f;
    }

    // ---------- warp reduction + write ----------
    float* o = out + (size_t)b * (NDIL * 2 * 2 * GG * KK)
                   + ((DI * 2 + diff) * 2) * (GG * KK) + g * KK;
    #pragma unroll
    for (int k = 0; k < KK; ++k){
      float vm = scm[(k << 5) + lane];
      float vn = scn[(k << 5) + lane];
      #pragma unroll
      for (int off = 16; off > 0; off >>= 1){
        vm += __shfl_xor_sync(0xffffffffu, vm, off);
        vn += __shfl_xor_sync(0xffffffffu, vn, off);
      }
      if (lane == 0){
        o[k]           = vm;
        o[GG * KK + k] = vn;
      }
    }
    __syncwarp();   // rowbuf reused by next task
  }
}

__global__ __launch_bounds__(BDIM, 1)
void hydra_kernel(const float* __restrict__ X,
                  const float* __restrict__ W,
                  const int*   __restrict__ I,
                  float* __restrict__ out)
{
  extern __shared__ float sm[];

  const int di = blockIdx.x;
  const int b  = blockIdx.y;
  const int tid = threadIdx.x;
  const int warp = tid >> 5, lane = tid & 31;

  float* row = sm + warp * ROWBUF;
  float* scm = sm + SCAT_OFF + warp * (KK * 32);
  float* scn = sm + SCAT_OFF + 16 * (KK * 32) + warp * (KK * 32);

  switch (di){
    case 0: run_di<0>(X, W, I, out, row, scm, scn, b, warp, lane); break;
    case 1: run_di<1>(X, W, I, out, row, scm, scn, b, warp, lane); break;
    case 2: run_di<2>(X, W, I, out, row, scm, scn, b, warp, lane); break;
    case 3: run_di<3>(X, W, I, out, row, scm, scn, b, warp, lane); break;
    case 4: run_di<4>(X, W, I, out, row, scm, scn, b, warp, lane); break;
    case 5: run_di<5>(X, W, I, out, row, scm, scn, b, warp, lane); break;
    case 6: run_di<6>(X, W, I, out, row, scm, scn, b, warp, lane); break;
    default: run_di<7>(X, W, I, out, row, scm, scn, b, warp, lane); break;
  }
}

extern "C" void kernel_launch(void* const* d_in, const int* in_sizes, int n_in,
                              void* d_out, int out_size)
{
  const float* X   = (const float*)d_in[0];   // [B, 12, 2048] f32
  const float* W   = (const float*)d_in[1];   // [8, 2, 256, 1, 9] f32
  const int*   I   = (const int*)  d_in[2];   // [8, 2, 32, 6] i32
  float*       out = (float*)d_out;           // [B, 8192] f32

  const int B = in_sizes[0] / (CC * LL);
  const size_t smem = (size_t)SMEM_FLOATS * sizeof(float);   // 229376 B

  cudaFuncSetAttribute(hydra_kernel,
                       cudaFuncAttributeMaxDynamicSharedMemorySize, (int)smem);

  dim3 grid(NDIL, B);
  hydra_kernel<<<grid, BDIM, smem>>>(X, W, I, out);
}

// round 5
// speedup vs baseline: 1.0497x; 1.0497x over previous
#include <cuda_runtime.h>

#define BDIM 512
#define LL   2048
#define CC   12
#define NDIL 8
#define KK   8
#define GG   32
#define NCP  6

#define SCAT_OFF (2 * CC * LL)                        // 49152 floats
#define SMEM_FLOATS (SCAT_OFF + 16 * KK * 32 * 2)     // 57344 floats = 229376 B

typedef unsigned long long u64;

__device__ __forceinline__ int swz(int x){ return x ^ (((x>>5)^(x>>10))&31); }

__device__ __forceinline__ u64 pack2(float lo, float hi){
  u64 r; asm("mov.b64 %0, {%1,%2};" : "=l"(r) : "f"(lo), "f"(hi)); return r;
}
__device__ __forceinline__ void unpack2(u64 v, float& lo, float& hi){
  asm("mov.b64 {%0,%1}, %2;" : "=f"(lo), "=f"(hi) : "l"(v));
}
__device__ __forceinline__ u64 ffma2(u64 a, u64 b, u64 c){
  u64 r; asm("fma.rn.f32x2 %0, %1, %2, %3;" : "=l"(r) : "l"(a), "l"(b), "l"(c)); return r;
}
__device__ __forceinline__ u64 fmul2(u64 a, u64 b){
  u64 r; asm("mul.rn.f32x2 %0, %1, %2;" : "=l"(r) : "l"(a), "l"(b)); return r;
}

// one summed tap; j is the tap's output-space index, valid iff 0 <= j < P
template<int DI>
__device__ __forceinline__ float tap(const float* __restrict__ sm, const int ro[6],
                                     int phase, int j){
  constexpr int d = 1 << DI;
  constexpr int P = LL >> DI;
  int x = (phase + j * d) & (LL - 1);
  int a = swz(x);
  float s = (sm[ro[0]+a] + sm[ro[1]+a]) + (sm[ro[2]+a] + sm[ro[3]+a])
          + (sm[ro[4]+a] + sm[ro[5]+a]);
  return ((unsigned)j < (unsigned)P) ? s : 0.0f;
}

// 8 dot products; window dup-packed as u64 (v,v)
__device__ __forceinline__ void dots8d(const u64 pk[36], const u64 w2[9], float a[8]){
  u64 a0 = fmul2(pk[0],  w2[0]), a1 = fmul2(pk[9],  w2[0]),
      a2 = fmul2(pk[18], w2[0]), a3 = fmul2(pk[27], w2[0]);
  #pragma unroll
  for (int t = 1; t < 9; ++t){
    a0 = ffma2(pk[t],      w2[t], a0);
    a1 = ffma2(pk[9 + t],  w2[t], a1);
    a2 = ffma2(pk[18 + t], w2[t], a2);
    a3 = ffma2(pk[27 + t], w2[t], a3);
  }
  unpack2(a0, a[0], a[1]); unpack2(a1, a[2], a[3]);
  unpack2(a2, a[4], a[5]); unpack2(a3, a[6], a[7]);
}

// tournament argmax/argmin over 8, exact first-occurrence tie-breaking
// (strict compare keeps the lower index on ties; left indices < right indices)
__device__ __forceinline__ void chain8(const float a[8], float& m, int& mi, int& ni){
  // level 1: 4 pairs
  float m0, m1, m2, m3, n0, n1, n2, n3;
  int mi0, mi1, mi2, mi3, ni0, ni1, ni2, ni3;
  m0 = fmaxf(a[0], a[1]); mi0 = (a[1] > a[0]) ? 1 : 0;
  m1 = fmaxf(a[2], a[3]); mi1 = (a[3] > a[2]) ? 3 : 2;
  m2 = fmaxf(a[4], a[5]); mi2 = (a[5] > a[4]) ? 5 : 4;
  m3 = fmaxf(a[6], a[7]); mi3 = (a[7] > a[6]) ? 7 : 6;
  n0 = fminf(a[0], a[1]); ni0 = (a[1] < a[0]) ? 1 : 0;
  n1 = fminf(a[2], a[3]); ni1 = (a[3] < a[2]) ? 3 : 2;
  n2 = fminf(a[4], a[5]); ni2 = (a[5] < a[4]) ? 5 : 4;
  n3 = fminf(a[6], a[7]); ni3 = (a[7] < a[6]) ? 7 : 6;
  // level 2
  float ma = fmaxf(m0, m1); int mia = (m1 > m0) ? mi1 : mi0;
  float mb = fmaxf(m2, m3); int mib = (m3 > m2) ? mi3 : mi2;
  float na = fminf(n0, n1); int nia = (n1 < n0) ? ni1 : ni0;
  float nb = fminf(n2, n3); int nib = (n3 < n2) ? ni3 : ni2;
  // level 3
  m  = fmaxf(ma, mb); mi = (mb > ma) ? mib : mia;
  ni = (nb < na) ? nib : nia;
}

template<int DI>
__device__ __forceinline__ void run_di(const float* __restrict__ sm,
                                       float* __restrict__ scm,
                                       float* __restrict__ scn,
                                       const float* __restrict__ W,
                                       const int*   __restrict__ I,
                                       float* __restrict__ out,
                                       int b, int warp, int lane)
{
  constexpr int d    = 1 << DI;
  constexpr int P    = LL >> DI;
  constexpr int logP = 11 - DI;
  constexpr int SEG  = (P < 64) ? P : 64;   // {64,64,64,64,64,64,32,16}
  constexpr int NSEG = 64 / SEG;

  for (int it = 0; it < 4; ++it){
    const int task = warp * 4 + it;
    const int diff = task >> 5, g = task & 31;

    const int* Ip = I + ((DI * 2 + diff) * GG + g) * NCP;
    int ro[6];
    #pragma unroll
    for (int j = 0; j < NCP; ++j) ro[j] = diff * CC * LL + __ldg(Ip + j) * LL;

    const float* Wp = W + (size_t)((DI * 2 + diff) * (KK * GG) + g * KK) * 9;
    u64 pk[36];   // pk[j*9+t] = (w[2j][t], w[2j+1][t])
    #pragma unroll
    for (int j = 0; j < 4; ++j)
      #pragma unroll
      for (int t = 0; t < 9; ++t)
        pk[j * 9 + t] = pack2(__ldg(Wp + (2 * j) * 9 + t),
                              __ldg(Wp + (2 * j + 1) * 9 + t));

    // zero this warp's private scatter columns (lane-private, no sync needed)
    #pragma unroll
    for (int k = 0; k < KK; ++k){
      scm[(k << 5) + lane] = 0.0f;
      scn[(k << 5) + lane] = 0.0f;
    }

    #pragma unroll
    for (int sg = 0; sg < NSEG; ++sg){
      const int q     = lane * 64 + sg * SEG;
      const int phase = q >> logP;
      const int j0    = q & (P - 1);

      u64 w2[9];
      #pragma unroll
      for (int t = 0; t < 9; ++t){
        float v = tap<DI>(sm, ro, phase, j0 + t - 4);
        w2[t] = pack2(v, v);
      }

      int j = j0;
      #pragma unroll 1
      for (int blk = 0; blk < SEG / 8; ++blk){
        #pragma unroll
        for (int u = 0; u < 8; ++u){
          // prefetch next tap FIRST: its 6 LDS issue before this position's
          // scatter STS, so the latency is covered by dots+chain below.
          float nv = tap<DI>(sm, ro, phase, j + 5);

          float a8[8]; float m; int mi, ni;
          dots8d(pk, w2, a8);
          chain8(a8, m, mi, ni);

          scm[(mi << 5) + lane] += m;      // register-indexed accumulate via smem
          scn[(ni << 5) + lane] += 1.0f;

          #pragma unroll
          for (int t = 0; t < 8; ++t) w2[t] = w2[t + 1];
          w2[8] = pack2(nv, nv);
          ++j;
        }
      }
    }

    // diff stream Lout = 2047: subtract phantom output position l = 2047
    // (always q = 2047 -> lane 31, phase = d-1, j = P-1; identical computation -> exact cancel)
    if (diff && lane == 31){
      u64 w9[9];
      #pragma unroll
      for (int t = 0; t < 9; ++t){
        float v = tap<DI>(sm, ro, d - 1, P - 1 + t - 4);
        w9[t] = pack2(v, v);
      }
      float a8[8]; float m; int mi, ni;
      dots8d(pk, w9, a8);
      chain8(a8, m, mi, ni);
      scm[(mi << 5) + 31] -= m;
      scn[(ni << 5) + 31] -= 1.0f;
    }

    // warp reduction from smem columns + write
    float* o = out + (size_t)b * (NDIL * 2 * 2 * GG * KK)
                   + ((DI * 2 + diff) * 2) * (GG * KK) + g * KK;
    #pragma unroll
    for (int k = 0; k < KK; ++k){
      float vm = scm[(k << 5) + lane];
      float vn = scn[(k << 5) + lane];
      #pragma unroll
      for (int off = 16; off > 0; off >>= 1){
        vm += __shfl_xor_sync(0xffffffffu, vm, off);
        vn += __shfl_xor_sync(0xffffffffu, vn, off);
      }
      if (lane == 0){
        o[k]           = vm;
        o[GG * KK + k] = vn;
      }
    }
  }
}

__global__ __launch_bounds__(BDIM, 1)
void hydra_kernel(const float* __restrict__ X,
                  const float* __restrict__ W,
                  const int*   __restrict__ I,
                  float* __restrict__ out)
{
  extern __shared__ float sm[];  // [0,C*L): X (swz), [C*L,2C*L): diff (diff[2047]=0), then scatter

  const int di = blockIdx.x;
  const int b  = blockIdx.y;
  const int tid = threadIdx.x;

  const float* Xb = X + (size_t)b * CC * LL;

  for (int i = tid; i < CC * LL; i += BDIM){
    int l = i & (LL - 1);
    float v  = Xb[i];
    float nv = (l < LL - 1) ? Xb[i + 1] : v;
    int a = swz(l);
    int c = i >> 11;
    sm[c * LL + a]           = v;
    sm[CC * LL + c * LL + a] = nv - v;
  }
  __syncthreads();

  const int warp = tid >> 5, lane = tid & 31;
  float* scm = sm + SCAT_OFF + warp * (KK * 32);
  float* scn = sm + SCAT_OFF + 16 * (KK * 32) + warp * (KK * 32);

  switch (di){
    case 0: run_di<0>(sm, scm, scn, W, I, out, b, warp, lane); break;
    case 1: run_di<1>(sm, scm, scn, W, I, out, b, warp, lane); break;
    case 2: run_di<2>(sm, scm, scn, W, I, out, b, warp, lane); break;
    case 3: run_di<3>(sm, scm, scn, W, I, out, b, warp, lane); break;
    case 4: run_di<4>(sm, scm, scn, W, I, out, b, warp, lane); break;
    case 5: run_di<5>(sm, scm, scn, W, I, out, b, warp, lane); break;
    case 6: run_di<6>(sm, scm, scn, W, I, out, b, warp, lane); break;
    default: run_di<7>(sm, scm, scn, W, I, out, b, warp, lane); break;
  }
}

extern "C" void kernel_launch(void* const* d_in, const int* in_sizes, int n_in,
                              void* d_out, int out_size)
{
  const float* X   = (const float*)d_in[0];   // [B, 12, 2048] f32
  const float* W   = (const float*)d_in[1];   // [8, 2, 256, 1, 9] f32
  const int*   I   = (const int*)  d_in[2];   // [8, 2, 32, 6] i32
  float*       out = (float*)d_out;           // [B, 8192] f32

  const int B = in_sizes[0] / (CC * LL);
  const size_t smem = (size_t)SMEM_FLOATS * sizeof(float);   // 229376 B

  cudaFuncSetAttribute(hydra_kernel,
                       cudaFuncAttributeMaxDynamicSharedMemorySize, (int)smem);

  dim3 grid(NDIL, B);
  hydra_kernel<<<grid, BDIM, smem>>>(X, W, I, out);
}

// round 6
// speedup vs baseline: 1.0721x; 1.0213x over previous
#include <cuda_runtime.h>

#define BDIM 512
#define LL   2048
#define CC   12
#define NDIL 8
#define KK   8
#define GG   32
#define NCP  6

#define SMEM_FLOATS (2 * CC * LL)   // 49152 floats = 196608 B

typedef unsigned long long u64;
typedef unsigned int u32;

__device__ __forceinline__ int swz(int x){ return x ^ (((x>>5)^(x>>10))&31); }

__device__ __forceinline__ u64 dup2(float v){
  u64 r; asm("mov.b64 %0, {%1,%1};" : "=l"(r) : "f"(v)); return r;
}
__device__ __forceinline__ void unpack2(u64 v, float& lo, float& hi){
  asm("mov.b64 {%0,%1}, %2;" : "=f"(lo), "=f"(hi) : "l"(v));
}
__device__ __forceinline__ u64 ffma2(u64 a, u64 b, u64 c){
  u64 r; asm("fma.rn.f32x2 %0, %1, %2, %3;" : "=l"(r) : "l"(a), "l"(b), "l"(c)); return r;
}
__device__ __forceinline__ u64 fmul2(u64 a, u64 b){
  u64 r; asm("mul.rn.f32x2 %0, %1, %2;" : "=l"(r) : "l"(a), "l"(b)); return r;
}

// one summed tap; jt is the tap's index in output space, valid iff 0 <= jt < P
template<int DI>
__device__ __forceinline__ float tap(const float* __restrict__ sm, const int ro[6],
                                     int phase, int jt){
  constexpr int d = 1 << DI;
  constexpr int P = LL >> DI;
  int x = (phase + jt * d) & (LL - 1);
  int a = swz(x);
  float s = (sm[ro[0]+a] + sm[ro[1]+a]) + (sm[ro[2]+a] + sm[ro[3]+a])
          + (sm[ro[4]+a] + sm[ro[5]+a]);
  return ((unsigned)jt < (unsigned)P) ? s : 0.0f;
}

// 8 dots from rotating window (rot static after unroll), then max/min trees
__device__ __forceinline__ void dots_mm(const u64 pk[36], const u64 w2[9], int rot,
                                        float a8[8], float& m, float& n){
  u64 b0 = w2[rot % 9];
  u64 a0 = fmul2(pk[0],  b0), a1 = fmul2(pk[9],  b0),
      a2 = fmul2(pk[18], b0), a3 = fmul2(pk[27], b0);
  #pragma unroll
  for (int t = 1; t < 9; ++t){
    u64 wt = w2[(rot + t) % 9];
    a0 = ffma2(pk[t],      wt, a0);
    a1 = ffma2(pk[9 + t],  wt, a1);
    a2 = ffma2(pk[18 + t], wt, a2);
    a3 = ffma2(pk[27 + t], wt, a3);
  }
  unpack2(a0, a8[0], a8[1]); unpack2(a1, a8[2], a8[3]);
  unpack2(a2, a8[4], a8[5]); unpack2(a3, a8[6], a8[7]);

  float m0 = fmaxf(a8[0], a8[1]), m1 = fmaxf(a8[2], a8[3]);
  float m2 = fmaxf(a8[4], a8[5]), m3 = fmaxf(a8[6], a8[7]);
  float n0 = fminf(a8[0], a8[1]), n1 = fminf(a8[2], a8[3]);
  float n2 = fminf(a8[4], a8[5]), n3 = fminf(a8[6], a8[7]);
  m = fmaxf(fmaxf(m0, m1), fmaxf(m2, m3));
  n = fminf(fminf(n0, n1), fminf(n2, n3));
}

template<int DI>
__device__ __forceinline__ void run_di(const float* __restrict__ sm,
                                       const float* __restrict__ W,
                                       const int*   __restrict__ I,
                                       float* __restrict__ out,
                                       int b, int warp, int lane)
{
  constexpr int d    = 1 << DI;
  constexpr int P    = LL >> DI;
  constexpr int logP = 11 - DI;
  constexpr int SEG  = (P < 64) ? P : 64;   // {64,...,64,32,16}
  constexpr int NSEG = 64 / SEG;
  constexpr int NB   = SEG / 9;             // full 9-position blocks
  constexpr int REM  = SEG - 9 * NB;        // static remainder (1,5,7)

  for (int it = 0; it < 4; ++it){
    const int task = warp * 4 + it;
    const int diff = task >> 5, g = task & 31;

    const int* Ip = I + ((DI * 2 + diff) * GG + g) * NCP;
    int ro[6];
    #pragma unroll
    for (int j = 0; j < NCP; ++j) ro[j] = diff * CC * LL + __ldg(Ip + j) * LL;

    const float* Wp = W + (size_t)((DI * 2 + diff) * (KK * GG) + g * KK) * 9;
    u64 pk[36];   // pk[j*9+t] = (w[2j][t], w[2j+1][t])
    #pragma unroll
    for (int j = 0; j < 4; ++j)
      #pragma unroll
      for (int t = 0; t < 9; ++t){
        float lo = __ldg(Wp + (2 * j) * 9 + t);
        float hi = __ldg(Wp + (2 * j + 1) * 9 + t);
        u64 r; asm("mov.b64 %0, {%1,%2};" : "=l"(r) : "f"(lo), "f"(hi));
        pk[j * 9 + t] = r;
      }

    float cm[8];
    #pragma unroll
    for (int k = 0; k < 8; ++k) cm[k] = 0.0f;
    u32 cnl = 0u, cnh = 0u;   // 4x8-bit min-count fields each (max 64/lane/task)

    #pragma unroll 1
    for (int sg = 0; sg < NSEG; ++sg){
      const int q     = lane * 64 + sg * SEG;
      const int phase = q >> logP;
      const int j0    = q & (P - 1);

      // initial window: tap (j0-4+t) -> slot t
      u64 w2[9];
      #pragma unroll
      for (int t = 0; t < 9; ++t)
        w2[t] = dup2(tap<DI>(sm, ro, phase, j0 - 4 + t));

      int jp = j0;
      #pragma unroll 1
      for (int blk = 0; blk < NB; ++blk){
        #pragma unroll
        for (int u = 0; u < 9; ++u){
          float nv = tap<DI>(sm, ro, phase, jp + u + 5);   // prefetch next tap
          float a8[8], m, n;
          dots_mm(pk, w2, u, a8, m, n);
          #pragma unroll
          for (int k = 0; k < 8; ++k){
            if (a8[k] == m) cm[k] += m;
            if (a8[k] == n){
              if (k < 4) cnl += 1u << (k * 8);
              else       cnh += 1u << ((k - 4) * 8);
            }
          }
          w2[u % 9] = dup2(nv);
        }
        jp += 9;
      }
      #pragma unroll
      for (int u = 0; u < REM; ++u){
        float nv = tap<DI>(sm, ro, phase, jp + u + 5);
        float a8[8], m, n;
        dots_mm(pk, w2, u, a8, m, n);
        #pragma unroll
        for (int k = 0; k < 8; ++k){
          if (a8[k] == m) cm[k] += m;
          if (a8[k] == n){
            if (k < 4) cnl += 1u << (k * 8);
            else       cnh += 1u << ((k - 4) * 8);
          }
        }
        w2[u % 9] = dup2(nv);
      }
    }

    // diff stream Lout = 2047: subtract phantom output position l = 2047
    // (always q = 2047 -> lane 31, phase = d-1, j = P-1; identical computation -> exact cancel)
    if (diff && lane == 31){
      u64 w9[9];
      #pragma unroll
      for (int t = 0; t < 9; ++t)
        w9[t] = dup2(tap<DI>(sm, ro, d - 1, P - 1 + t - 4));
      float a8[8], m, n;
      dots_mm(pk, w9, 0, a8, m, n);
      #pragma unroll
      for (int k = 0; k < 8; ++k){
        if (a8[k] == m) cm[k] -= m;
        if (a8[k] == n){
          if (k < 4) cnl -= 1u << (k * 8);
          else       cnh -= 1u << ((k - 4) * 8);
        }
      }
    }

    // cross-lane reduction + write
    float cn[8];
    #pragma unroll
    for (int k = 0; k < 4; ++k){
      cn[k]     = (float)((cnl >> (k * 8)) & 0xffu);
      cn[k + 4] = (float)((cnh >> (k * 8)) & 0xffu);
    }
    #pragma unroll
    for (int k = 0; k < 8; ++k){
      #pragma unroll
      for (int off = 16; off > 0; off >>= 1){
        cm[k] += __shfl_xor_sync(0xffffffffu, cm[k], off);
        cn[k] += __shfl_xor_sync(0xffffffffu, cn[k], off);
      }
    }
    if (lane == 0){
      float* o = out + (size_t)b * (NDIL * 2 * 2 * GG * KK)
                     + ((DI * 2 + diff) * 2) * (GG * KK) + g * KK;
      #pragma unroll
      for (int k = 0; k < 8; ++k){
        o[k]           = cm[k];
        o[GG * KK + k] = cn[k];
      }
    }
  }
}

__global__ __launch_bounds__(BDIM, 1)
void hydra_kernel(const float* __restrict__ X,
                  const float* __restrict__ W,
                  const int*   __restrict__ I,
                  float* __restrict__ out)
{
  extern __shared__ float sm[];  // [0,C*L): X (swz), [C*L,2C*L): diff (diff[2047]=0)

  const int di = blockIdx.x;
  const int b  = blockIdx.y;
  const int tid = threadIdx.x;

  const float* Xb = X + (size_t)b * CC * LL;

  for (int i = tid; i < CC * LL; i += BDIM){
    int l = i & (LL - 1);
    float v  = Xb[i];
    float nv = (l < LL - 1) ? Xb[i + 1] : v;
    int a = swz(l);
    int c = i >> 11;
    sm[c * LL + a]           = v;
    sm[CC * LL + c * LL + a] = nv - v;
  }
  __syncthreads();

  const int warp = tid >> 5, lane = tid & 31;

  switch (di){
    case 0: run_di<0>(sm, W, I, out, b, warp, lane); break;
    case 1: run_di<1>(sm, W, I, out, b, warp, lane); break;
    case 2: run_di<2>(sm, W, I, out, b, warp, lane); break;
    case 3: run_di<3>(sm, W, I, out, b, warp, lane); break;
    case 4: run_di<4>(sm, W, I, out, b, warp, lane); break;
    case 5: run_di<5>(sm, W, I, out, b, warp, lane); break;
    case 6: run_di<6>(sm, W, I, out, b, warp, lane); break;
    default: run_di<7>(sm, W, I, out, b, warp, lane); break;
  }
}

extern "C" void kernel_launch(void* const* d_in, const int* in_sizes, int n_in,
                              void* d_out, int out_size)
{
  const float* X   = (const float*)d_in[0];   // [B, 12, 2048] f32
  const float* W   = (const float*)d_in[1];   // [8, 2, 256, 1, 9] f32
  const int*   I   = (const int*)  d_in[2];   // [8, 2, 32, 6] i32
  float*       out = (float*)d_out;           // [B, 8192] f32

  const int B = in_sizes[0] / (CC * LL);
  const size_t smem = (size_t)SMEM_FLOATS * sizeof(float);   // 196608 B

  cudaFuncSetAttribute(hydra_kernel,
                       cudaFuncAttributeMaxDynamicSharedMemorySize, (int)smem);

  dim3 grid(NDIL, B);
  hydra_kernel<<<grid, BDIM, smem>>>(X, W, I, out);
}

// round 7
// speedup vs baseline: 1.0739x; 1.0016x over previous
#include <cuda_runtime.h>

#define BDIM 512
#define LL   2048
#define CC   12
#define NDIL 8
#define KK   8
#define GG   32
#define NCP  6

#define SMEM_FLOATS (2 * CC * LL)   // 49152 floats = 196608 B

typedef unsigned long long u64;
typedef unsigned int u32;

__device__ __forceinline__ int swz(int x){ return x ^ (((x>>5)^(x>>10))&31); }

__device__ __forceinline__ u64 dup2(float v){
  u64 r; asm("mov.b64 %0, {%1,%1};" : "=l"(r) : "f"(v)); return r;
}
__device__ __forceinline__ void unpack2(u64 v, float& lo, float& hi){
  asm("mov.b64 {%0,%1}, %2;" : "=f"(lo), "=f"(hi) : "l"(v));
}
__device__ __forceinline__ u64 ffma2(u64 a, u64 b, u64 c){
  u64 r; asm("fma.rn.f32x2 %0, %1, %2, %3;" : "=l"(r) : "l"(a), "l"(b), "l"(c)); return r;
}
__device__ __forceinline__ u64 fmul2(u64 a, u64 b){
  u64 r; asm("mul.rn.f32x2 %0, %1, %2;" : "=l"(r) : "l"(a), "l"(b)); return r;
}

// one summed tap; jt is the tap's index in output space, valid iff 0 <= jt < P
template<int DI>
__device__ __forceinline__ float tap(const float* __restrict__ sm, const int ro[6],
                                     int phase, int jt){
  constexpr int d = 1 << DI;
  constexpr int P = LL >> DI;
  int x = (phase + jt * d) & (LL - 1);
  int a = swz(x);
  float s = (sm[ro[0]+a] + sm[ro[1]+a]) + (sm[ro[2]+a] + sm[ro[3]+a])
          + (sm[ro[4]+a] + sm[ro[5]+a]);
  return ((unsigned)jt < (unsigned)P) ? s : 0.0f;
}

// 8 dots from rotating window (rot static after unroll), then max/min trees
__device__ __forceinline__ void dots_mm(const u64 pk[36], const u64 w2[9], int rot,
                                        float a8[8], float& m, float& n){
  u64 b0 = w2[rot % 9];
  u64 a0 = fmul2(pk[0],  b0), a1 = fmul2(pk[9],  b0),
      a2 = fmul2(pk[18], b0), a3 = fmul2(pk[27], b0);
  #pragma unroll
  for (int t = 1; t < 9; ++t){
    u64 wt = w2[(rot + t) % 9];
    a0 = ffma2(pk[t],      wt, a0);
    a1 = ffma2(pk[9 + t],  wt, a1);
    a2 = ffma2(pk[18 + t], wt, a2);
    a3 = ffma2(pk[27 + t], wt, a3);
  }
  unpack2(a0, a8[0], a8[1]); unpack2(a1, a8[2], a8[3]);
  unpack2(a2, a8[4], a8[5]); unpack2(a3, a8[6], a8[7]);

  float m0 = fmaxf(a8[0], a8[1]), m1 = fmaxf(a8[2], a8[3]);
  float m2 = fmaxf(a8[4], a8[5]), m3 = fmaxf(a8[6], a8[7]);
  float n0 = fminf(a8[0], a8[1]), n1 = fminf(a8[2], a8[3]);
  float n2 = fminf(a8[4], a8[5]), n3 = fminf(a8[6], a8[7]);
  m = fmaxf(fmaxf(m0, m1), fmaxf(m2, m3));
  n = fminf(fminf(n0, n1), fminf(n2, n3));
}

template<int DI>
__device__ __forceinline__ void run_di(const float* __restrict__ sm,
                                       const float* __restrict__ W,
                                       const int*   __restrict__ I,
                                       float* __restrict__ out,
                                       int b, int warp, int lane)
{
  constexpr int d    = 1 << DI;
  constexpr int P    = LL >> DI;
  constexpr int logP = 11 - DI;
  constexpr int SEG  = (P < 64) ? P : 64;   // {64,...,64,32,16}
  constexpr int NSEG = 64 / SEG;
  constexpr int NB   = SEG / 9;             // full 9-position blocks
  constexpr int REM  = SEG - 9 * NB;        // static remainder (1,5,7)

  for (int it = 0; it < 4; ++it){
    const int task = warp * 4 + it;
    const int diff = task >> 5, g = task & 31;

    const int* Ip = I + ((DI * 2 + diff) * GG + g) * NCP;
    int ro[6];
    #pragma unroll
    for (int j = 0; j < NCP; ++j) ro[j] = diff * CC * LL + __ldg(Ip + j) * LL;

    const float* Wp = W + (size_t)((DI * 2 + diff) * (KK * GG) + g * KK) * 9;
    u64 pk[36];   // pk[j*9+t] = (w[2j][t], w[2j+1][t])
    #pragma unroll
    for (int j = 0; j < 4; ++j)
      #pragma unroll
      for (int t = 0; t < 9; ++t){
        float lo = __ldg(Wp + (2 * j) * 9 + t);
        float hi = __ldg(Wp + (2 * j + 1) * 9 + t);
        u64 r; asm("mov.b64 %0, {%1,%2};" : "=l"(r) : "f"(lo), "f"(hi));
        pk[j * 9 + t] = r;
      }

    float cm[8];
    #pragma unroll
    for (int k = 0; k < 8; ++k) cm[k] = 0.0f;
    u32 cnl = 0u, cnh = 0u;   // 4x8-bit min-count fields each (max 64/lane/task)

    #pragma unroll 1
    for (int sg = 0; sg < NSEG; ++sg){
      const int q     = lane * 64 + sg * SEG;
      const int phase = q >> logP;
      const int j0    = q & (P - 1);

      // initial window: tap (j0-4+t) -> slot t
      u64 w2[9];
      #pragma unroll
      for (int t = 0; t < 9; ++t)
        w2[t] = dup2(tap<DI>(sm, ro, phase, j0 - 4 + t));

      int jp = j0;
      #pragma unroll 1
      for (int blk = 0; blk < NB; ++blk){
        #pragma unroll
        for (int u = 0; u < 9; ++u){
          float nv = tap<DI>(sm, ro, phase, jp + u + 5);   // prefetch next tap
          float a8[8], m, n;
          dots_mm(pk, w2, u, a8, m, n);
          #pragma unroll
          for (int k = 0; k < 8; ++k){
            if (a8[k] == m) cm[k] += m;
            if (a8[k] == n){
              if (k < 4) cnl += 1u << (k * 8);
              else       cnh += 1u << ((k - 4) * 8);
            }
          }
          w2[u % 9] = dup2(nv);
        }
        jp += 9;
      }
      #pragma unroll
      for (int u = 0; u < REM; ++u){
        float nv = tap<DI>(sm, ro, phase, jp + u + 5);
        float a8[8], m, n;
        dots_mm(pk, w2, u, a8, m, n);
        #pragma unroll
        for (int k = 0; k < 8; ++k){
          if (a8[k] == m) cm[k] += m;
          if (a8[k] == n){
            if (k < 4) cnl += 1u << (k * 8);
            else       cnh += 1u << ((k - 4) * 8);
          }
        }
        w2[u % 9] = dup2(nv);
      }
    }

    // diff stream Lout = 2047: subtract phantom output position l = 2047
    // (always q = 2047 -> lane 31, phase = d-1, j = P-1; identical computation -> exact cancel)
    if (diff && lane == 31){
      u64 w9[9];
      #pragma unroll
      for (int t = 0; t < 9; ++t)
        w9[t] = dup2(tap<DI>(sm, ro, d - 1, P - 1 + t - 4));
      float a8[8], m, n;
      dots_mm(pk, w9, 0, a8, m, n);
      #pragma unroll
      for (int k = 0; k < 8; ++k){
        if (a8[k] == m) cm[k] -= m;
        if (a8[k] == n){
          if (k < 4) cnl -= 1u << (k * 8);
          else       cnh -= 1u << ((k - 4) * 8);
        }
      }
    }

    // cross-lane reduction + write
    float cn[8];
    #pragma unroll
    for (int k = 0; k < 4; ++k){
      cn[k]     = (float)((cnl >> (k * 8)) & 0xffu);
      cn[k + 4] = (float)((cnh >> (k * 8)) & 0xffu);
    }
    #pragma unroll
    for (int k = 0; k < 8; ++k){
      #pragma unroll
      for (int off = 16; off > 0; off >>= 1){
        cm[k] += __shfl_xor_sync(0xffffffffu, cm[k], off);
        cn[k] += __shfl_xor_sync(0xffffffffu, cn[k], off);
      }
    }
    if (lane == 0){
      float* o = out + (size_t)b * (NDIL * 2 * 2 * GG * KK)
                     + ((DI * 2 + diff) * 2) * (GG * KK) + g * KK;
      #pragma unroll
      for (int k = 0; k < 8; ++k){
        o[k]           = cm[k];
        o[GG * KK + k] = cn[k];
      }
    }
  }
}

__global__ __launch_bounds__(BDIM, 1)
void hydra_kernel(const float* __restrict__ X,
                  const float* __restrict__ W,
                  const int*   __restrict__ I,
                  float* __restrict__ out)
{
  extern __shared__ float sm[];  // [0,C*L): X (swz), [C*L,2C*L): diff (diff[2047]=0)

  const int di = blockIdx.x;
  const int b  = blockIdx.y;
  const int tid = threadIdx.x;

  const float* Xb = X + (size_t)b * CC * LL;

  for (int i = tid; i < CC * LL; i += BDIM){
    int l = i & (LL - 1);
    float v  = Xb[i];
    float nv = (l < LL - 1) ? Xb[i + 1] : v;
    int a = swz(l);
    int c = i >> 11;
    sm[c * LL + a]           = v;
    sm[CC * LL + c * LL + a] = nv - v;
  }
  __syncthreads();

  const int warp = tid >> 5, lane = tid & 31;

  switch (di){
    case 0: run_di<0>(sm, W, I, out, b, warp, lane); break;
    case 1: run_di<1>(sm, W, I, out, b, warp, lane); break;
    case 2: run_di<2>(sm, W, I, out, b, warp, lane); break;
    case 3: run_di<3>(sm, W, I, out, b, warp, lane); break;
    case 4: run_di<4>(sm, W, I, out, b, warp, lane); break;
    case 5: run_di<5>(sm, W, I, out, b, warp, lane); break;
    case 6: run_di<6>(sm, W, I, out, b, warp, lane); break;
    default: run_di<7>(sm, W, I, out, b, warp, lane); break;
  }
}

extern "C" void kernel_launch(void* const* d_in, const int* in_sizes, int n_in,
                              void* d_out, int out_size)
{
  const float* X   = (const float*)d_in[0];   // [B, 12, 2048] f32
  const float* W   = (const float*)d_in[1];   // [8, 2, 256, 1, 9] f32
  const int*   I   = (const int*)  d_in[2];   // [8, 2, 32, 6] i32
  float*       out = (float*)d_out;           // [B, 8192] f32

  const int B = in_sizes[0] / (CC * LL);
  const size_t smem = (size_t)SMEM_FLOATS * sizeof(float);   // 196608 B

  cudaFuncSetAttribute(hydra_kernel,
                       cudaFuncAttributeMaxDynamicSharedMemorySize, (int)smem);

  dim3 grid(NDIL, B);
  hydra_kernel<<<grid, BDIM, smem>>>(X, W, I, out);
}

// round 8
// speedup vs baseline: 1.1647x; 1.0846x over previous
#include <cuda_runtime.h>

#define BDIM 512
#define LL   2048
#define CC   12
#define NDIL 8
#define KK   8
#define GG   32
#define NCP  6

#define SCAT_OFF (2 * CC * LL)                        // 49152 floats
#define SMEM_FLOATS (SCAT_OFF + 16 * KK * 32 * 2)     // 57344 floats = 229376 B

typedef unsigned long long u64;
typedef unsigned int u32;

__device__ __forceinline__ int swz(int x){ return x ^ (((x>>5)^(x>>10))&31); }

__device__ __forceinline__ u64 dup2(float v){
  u64 r; asm("mov.b64 %0, {%1,%1};" : "=l"(r) : "f"(v)); return r;
}
__device__ __forceinline__ void unpack2(u64 v, float& lo, float& hi){
  asm("mov.b64 {%0,%1}, %2;" : "=f"(lo), "=f"(hi) : "l"(v));
}
__device__ __forceinline__ u64 ffma2(u64 a, u64 b, u64 c){
  u64 r; asm("fma.rn.f32x2 %0, %1, %2, %3;" : "=l"(r) : "l"(a), "l"(b), "l"(c)); return r;
}
__device__ __forceinline__ u64 fmul2(u64 a, u64 b){
  u64 r; asm("mul.rn.f32x2 %0, %1, %2;" : "=l"(r) : "l"(a), "l"(b)); return r;
}
// embed k into low 3 mantissa bits: one LOP3
__device__ __forceinline__ float embed(float v, int k){
  u32 b = (__float_as_uint(v) & ~7u) | (u32)k;
  return __uint_as_float(b);
}

// one summed tap; jt is the tap's index in output space, valid iff 0 <= jt < P
template<int DI>
__device__ __forceinline__ float tap(const float* __restrict__ sm, const int ro[6],
                                     int phase, int jt){
  constexpr int d = 1 << DI;
  constexpr int P = LL >> DI;
  int x = (phase + jt * d) & (LL - 1);
  int a = swz(x);
  float s = (sm[ro[0]+a] + sm[ro[1]+a]) + (sm[ro[2]+a] + sm[ro[3]+a])
          + (sm[ro[4]+a] + sm[ro[5]+a]);
  return ((unsigned)jt < (unsigned)P) ? s : 0.0f;
}

// 8 dots (rotating window), index-embedded max/min tournament.
// m/n carry the winning k in their low 3 bits.
__device__ __forceinline__ void dots_mm(const u64 pk[36], const u64 w2[9], int rot,
                                        float& m, float& n){
  u64 b0 = w2[rot % 9];
  u64 a0 = fmul2(pk[0],  b0), a1 = fmul2(pk[9],  b0),
      a2 = fmul2(pk[18], b0), a3 = fmul2(pk[27], b0);
  #pragma unroll
  for (int t = 1; t < 9; ++t){
    u64 wt = w2[(rot + t) % 9];
    a0 = ffma2(pk[t],      wt, a0);
    a1 = ffma2(pk[9 + t],  wt, a1);
    a2 = ffma2(pk[18 + t], wt, a2);
    a3 = ffma2(pk[27 + t], wt, a3);
  }
  float a8[8];
  unpack2(a0, a8[0], a8[1]); unpack2(a1, a8[2], a8[3]);
  unpack2(a2, a8[4], a8[5]); unpack2(a3, a8[6], a8[7]);

  float e0 = embed(a8[0], 0), e1 = embed(a8[1], 1);
  float e2 = embed(a8[2], 2), e3 = embed(a8[3], 3);
  float e4 = embed(a8[4], 4), e5 = embed(a8[5], 5);
  float e6 = embed(a8[6], 6), e7 = embed(a8[7], 7);

  m = fmaxf(fmaxf(fmaxf(e0, e1), fmaxf(e2, e3)),
            fmaxf(fmaxf(e4, e5), fmaxf(e6, e7)));
  n = fminf(fminf(fminf(e0, e1), fminf(e2, e3)),
            fminf(fminf(e4, e5), fminf(e6, e7)));
}

template<int DI>
__device__ __forceinline__ void run_di(const float* __restrict__ sm,
                                       float* __restrict__ scm,
                                       float* __restrict__ scn,
                                       const float* __restrict__ W,
                                       const int*   __restrict__ I,
                                       float* __restrict__ out,
                                       int b, int warp, int lane)
{
  constexpr int d    = 1 << DI;
  constexpr int P    = LL >> DI;
  constexpr int logP = 11 - DI;
  constexpr int SEG  = (P < 64) ? P : 64;   // {64,...,64,32,16}
  constexpr int NSEG = 64 / SEG;
  constexpr int NB   = SEG / 9;             // full 9-position blocks
  constexpr int REM  = SEG - 9 * NB;        // static remainder

  for (int it = 0; it < 4; ++it){
    const int task = warp * 4 + it;
    const int diff = task >> 5, g = task & 31;

    const int* Ip = I + ((DI * 2 + diff) * GG + g) * NCP;
    int ro[6];
    #pragma unroll
    for (int j = 0; j < NCP; ++j) ro[j] = diff * CC * LL + __ldg(Ip + j) * LL;

    const float* Wp = W + (size_t)((DI * 2 + diff) * (KK * GG) + g * KK) * 9;
    u64 pk[36];   // pk[j*9+t] = (w[2j][t], w[2j+1][t])
    #pragma unroll
    for (int j = 0; j < 4; ++j)
      #pragma unroll
      for (int t = 0; t < 9; ++t){
        float lo = __ldg(Wp + (2 * j) * 9 + t);
        float hi = __ldg(Wp + (2 * j + 1) * 9 + t);
        u64 r; asm("mov.b64 %0, {%1,%2};" : "=l"(r) : "f"(lo), "f"(hi));
        pk[j * 9 + t] = r;
      }

    // zero this warp's private scatter columns (lane-private, no sync needed)
    #pragma unroll
    for (int k = 0; k < KK; ++k){
      scm[(k << 5) + lane] = 0.0f;
      scn[(k << 5) + lane] = 0.0f;
    }

    #pragma unroll 1
    for (int sg = 0; sg < NSEG; ++sg){
      const int q     = lane * 64 + sg * SEG;
      const int phase = q >> logP;
      const int j0    = q & (P - 1);

      u64 w2[9];
      #pragma unroll
      for (int t = 0; t < 9; ++t)
        w2[t] = dup2(tap<DI>(sm, ro, phase, j0 - 4 + t));

      int jp = j0;
      #pragma unroll 1
      for (int blk = 0; blk < NB; ++blk){
        #pragma unroll
        for (int u = 0; u < 9; ++u){
          float nv = tap<DI>(sm, ro, phase, jp + u + 5);   // prefetch next tap
          float m, n;
          dots_mm(pk, w2, u, m, n);
          int mk = (int)(__float_as_uint(m) & 7u);
          int nk = (int)(__float_as_uint(n) & 7u);
          scm[(mk << 5) + lane] += m;       // embedded value ≈ m (≤7 ulp)
          scn[(nk << 5) + lane] += 1.0f;
          w2[u % 9] = dup2(nv);
        }
        jp += 9;
      }
      #pragma unroll
      for (int u = 0; u < REM; ++u){
        float nv = tap<DI>(sm, ro, phase, jp + u + 5);
        float m, n;
        dots_mm(pk, w2, u, m, n);
        int mk = (int)(__float_as_uint(m) & 7u);
        int nk = (int)(__float_as_uint(n) & 7u);
        scm[(mk << 5) + lane] += m;
        scn[(nk << 5) + lane] += 1.0f;
        w2[u % 9] = dup2(nv);
      }
    }

    // diff stream Lout = 2047: subtract phantom output position l = 2047
    // (q = 2047 -> lane 31, phase = d-1, j = P-1; bitwise-identical recompute -> exact cancel)
    if (diff && lane == 31){
      u64 w9[9];
      #pragma unroll
      for (int t = 0; t < 9; ++t)
        w9[t] = dup2(tap<DI>(sm, ro, d - 1, P - 1 + t - 4));
      float m, n;
      dots_mm(pk, w9, 0, m, n);
      int mk = (int)(__float_as_uint(m) & 7u);
      int nk = (int)(__float_as_uint(n) & 7u);
      scm[(mk << 5) + 31] -= m;
      scn[(nk << 5) + 31] -= 1.0f;
    }

    // cross-lane reduction from smem columns + write
    float* o = out + (size_t)b * (NDIL * 2 * 2 * GG * KK)
                   + ((DI * 2 + diff) * 2) * (GG * KK) + g * KK;
    #pragma unroll
    for (int k = 0; k < KK; ++k){
      float vm = scm[(k << 5) + lane];
      float vn = scn[(k << 5) + lane];
      #pragma unroll
      for (int off = 16; off > 0; off >>= 1){
        vm += __shfl_xor_sync(0xffffffffu, vm, off);
        vn += __shfl_xor_sync(0xffffffffu, vn, off);
      }
      if (lane == 0){
        o[k]           = vm;
        o[GG * KK + k] = vn;
      }
    }
  }
}

__global__ __launch_bounds__(BDIM, 1)
void hydra_kernel(const float* __restrict__ X,
                  const float* __restrict__ W,
                  const int*   __restrict__ I,
                  float* __restrict__ out)
{
  extern __shared__ float sm[];  // X (swz) | diff (diff[2047]=0) | scatter columns

  const int di = blockIdx.x;
  const int b  = blockIdx.y;
  const int tid = threadIdx.x;

  const float* Xb = X + (size_t)b * CC * LL;

  for (int i = tid; i < CC * LL; i += BDIM){
    int l = i & (LL - 1);
    float v  = Xb[i];
    float nv = (l < LL - 1) ? Xb[i + 1] : v;
    int a = swz(l);
    int c = i >> 11;
    sm[c * LL + a]           = v;
    sm[CC * LL + c * LL + a] = nv - v;
  }
  __syncthreads();

  const int warp = tid >> 5, lane = tid & 31;
  float* scm = sm + SCAT_OFF + warp * (KK * 32);
  float* scn = sm + SCAT_OFF + 16 * (KK * 32) + warp * (KK * 32);

  switch (di){
    case 0: run_di<0>(sm, scm, scn, W, I, out, b, warp, lane); break;
    case 1: run_di<1>(sm, scm, scn, W, I, out, b, warp, lane); break;
    case 2: run_di<2>(sm, scm, scn, W, I, out, b, warp, lane); break;
    case 3: run_di<3>(sm, scm, scn, W, I, out, b, warp, lane); break;
    case 4: run_di<4>(sm, scm, scn, W, I, out, b, warp, lane); break;
    case 5: run_di<5>(sm, scm, scn, W, I, out, b, warp, lane); break;
    case 6: run_di<6>(sm, scm, scn, W, I, out, b, warp, lane); break;
    default: run_di<7>(sm, scm, scn, W, I, out, b, warp, lane); break;
  }
}

extern "C" void kernel_launch(void* const* d_in, const int* in_sizes, int n_in,
                              void* d_out, int out_size)
{
  const float* X   = (const float*)d_in[0];   // [B, 12, 2048] f32
  const float* W   = (const float*)d_in[1];   // [8, 2, 256, 1, 9] f32
  const int*   I   = (const int*)  d_in[2];   // [8, 2, 32, 6] i32
  float*       out = (float*)d_out;           // [B, 8192] f32

  const int B = in_sizes[0] / (CC * LL);
  const size_t smem = (size_t)SMEM_FLOATS * sizeof(float);   // 229376 B

  cudaFuncSetAttribute(hydra_kernel,
                       cudaFuncAttributeMaxDynamicSharedMemorySize, (int)smem);

  dim3 grid(NDIL, B);
  hydra_kernel<<<grid, BDIM, smem>>>(X, W, I, out);
}